// round 16
// baseline (speedup 1.0000x reference)
#include <cuda_runtime.h>
#include <cuda_fp16.h>
#include <cstdint>
#include <math.h>

#define N_NODES     500000
#define HIDDEN      256
#define NUM_CLASSES 104
#define AUX_DIM     2
#define NUM_GRAPHS  2048
#define D_IN        (NUM_CLASSES + AUX_DIM)   // 106
#define GRAPH_X     128
#define CP          128                        // padded class dim

// smem layout (units: halves)
#define WG_ST   520
#define WT_ST   264
#define AS_ST   40
#define WG_OFF  0
#define WT_OFF  66560
#define A_OFF   100352
#define A_BUF   (128 * AS_ST)
#define DYN_BYTES ((A_OFF + 2 * A_BUF) * 2)    // 221184 bytes

// ---------------- device scratch ----------------
__device__ __half g_Wg_h[CP * 2 * HIDDEN];
__device__ __half g_Wt_h[CP * HIDDEN];
__device__ float  g_bg_pad[CP];
__device__ float  g_bt_pad[CP];
__device__ int    g_start[NUM_GRAPHS + 1];
__device__ float  g_readout[NUM_GRAPHS * NUM_CLASSES];

// ---------------- PTX helpers (portable, no 'a' features) ----------------
__device__ __forceinline__ void cp16(uint32_t dst_smem, const void* src) {
    asm volatile("cp.async.cg.shared.global [%0], [%1], 16;" :: "r"(dst_smem), "l"(src));
}
#define CP_COMMIT() asm volatile("cp.async.commit_group;" ::: "memory")
#define CP_WAIT0()  asm volatile("cp.async.wait_group 0;" ::: "memory")

__device__ __forceinline__ uint32_t pack2(float lo, float hi) {
    uint32_t r;
    asm("cvt.rn.f16x2.f32 %0, %1, %2;" : "=r"(r) : "f"(hi), "f"(lo));
    return r;
}
__device__ __forceinline__ void mma16(float c[4], const uint32_t a[4], uint32_t b0, uint32_t b1) {
    asm volatile(
        "mma.sync.aligned.m16n8k16.row.col.f32.f16.f16.f32 "
        "{%0,%1,%2,%3}, {%4,%5,%6,%7}, {%8,%9}, {%0,%1,%2,%3};"
        : "+f"(c[0]), "+f"(c[1]), "+f"(c[2]), "+f"(c[3])
        : "r"(a[0]), "r"(a[1]), "r"(a[2]), "r"(a[3]), "r"(b0), "r"(b1));
}
__device__ __forceinline__ void ldsm4(uint32_t r[4], uint32_t addr) {
    asm volatile("ldmatrix.sync.aligned.m8n8.x4.shared.b16 {%0,%1,%2,%3}, [%4];"
                 : "=r"(r[0]), "=r"(r[1]), "=r"(r[2]), "=r"(r[3]) : "r"(addr));
}

// ---------------- prep ----------------
__global__ void prep_kernel(const float* __restrict__ Wg, const float* __restrict__ bg,
                            const float* __restrict__ Wt, const float* __restrict__ bt) {
    int i = blockIdx.x * blockDim.x + threadIdx.x;
    if (i < CP * 2 * HIDDEN) {
        int n = i >> 9, k = i & 511;
        g_Wg_h[i] = __float2half_rn((n < NUM_CLASSES) ? Wg[k * NUM_CLASSES + n] : 0.f);
    }
    if (i < CP * HIDDEN) {
        int n = i >> 8, k = i & 255;
        g_Wt_h[i] = __float2half_rn((n < NUM_CLASSES) ? Wt[k * NUM_CLASSES + n] : 0.f);
    }
    if (i < CP) {
        g_bg_pad[i] = (i < NUM_CLASSES) ? bg[i] : 0.f;
        g_bt_pad[i] = (i < NUM_CLASSES) ? bt[i] : 0.f;
    }
}

// ---------------- graph segment starts ----------------
__global__ void starts_kernel(const int* __restrict__ gl, int n) {
    int g = blockIdx.x * blockDim.x + threadIdx.x;
    if (g > NUM_GRAPHS) return;
    int lo = 0, hi = n;
    while (lo < hi) {
        int mid = (lo + hi) >> 1;
        if (gl[mid] < g) lo = mid + 1; else hi = mid;
    }
    g_start[g] = lo;
}

// ---------------- dummy: shifts ncu -s window onto fused_node_tc ----------------
__global__ void align_dummy_kernel() {}

// ---------------- main fused kernel: PERSISTENT blocks, 1024 thr (32 warps) ----------------
// Warp layout: 8 column-warps (16 cols each) x 4 row-quarter-warps (32 rows each).
// Per-thread accumulators: 32 (vs 64 at 512 thr) -> target <=64 regs -> occ 50%.
__global__ __launch_bounds__(1024, 1) void fused_node_tc(
        const float* __restrict__ xi, const float* __restrict__ xf) {
    extern __shared__ __half sm[];

    const int tid  = threadIdx.x;
    const int lane = tid & 31;
    const int wid  = tid >> 5;
    const int gid  = lane >> 2;
    const int tig  = lane & 3;
    const int wc   = wid & 7;       // column warp group (16 cols)
    const int rq   = wid >> 3;      // row quarter (0..3, 32 rows)
    const int nb   = wc * 16;
    const int rb   = rq * 32;

    const uint32_t smu = (uint32_t)__cvta_generic_to_shared(sm);

    // ---- load ALL weights into smem once per block ----
    #pragma unroll
    for (int i = 0; i < 8; i++) {
        int idx = i * 1024 + tid;
        int n = idx >> 6, kq = idx & 63;
        cp16(smu + (uint32_t)(WG_OFF + n * WG_ST + kq * 8) * 2u, g_Wg_h + n * 512 + kq * 8);
    }
    #pragma unroll
    for (int i = 0; i < 4; i++) {
        int idx = i * 1024 + tid;
        int n = idx >> 5, kq = idx & 31;
        cp16(smu + (uint32_t)(WT_OFF + n * WT_ST + kq * 8) * 2u, g_Wt_h + n * 256 + kq * 8);
    }
    CP_COMMIT();

    // ldmatrix base addresses (bytes)
    const uint32_t aBase = smu + 2u * (uint32_t)(A_OFF + (rb + (lane & 15)) * AS_ST
                                                 + ((lane >> 4) & 1) * 8);
    const int wrow = nb + (lane & 7) + ((lane >> 4) & 1) * 8;
    const uint32_t wgBase = smu + 2u * (uint32_t)(WG_OFF + wrow * WG_ST + ((lane >> 3) & 1) * 8);
    const uint32_t wtBase = smu + 2u * (uint32_t)(WT_OFF + wrow * WT_ST + ((lane >> 3) & 1) * 8);

    const int ar  = tid >> 3;        // A staging: row 0..127
    const int acq = (tid & 7) * 4;   // col chunk (4 floats)

    CP_WAIT0();
    __syncthreads();

    for (int g = blockIdx.x; g < NUM_GRAPHS; g += gridDim.x) {
        const int s0 = g_start[g], e = g_start[g + 1];
        float sumE[2] = {0.f, 0.f}, sumO[2] = {0.f, 0.f};

        for (int t0 = s0; t0 < e; t0 += 128) {
            float accG[2][2][4], accT[2][2][4];
            #pragma unroll
            for (int rg = 0; rg < 2; rg++)
                #pragma unroll
                for (int nt = 0; nt < 2; nt++)
                    #pragma unroll
                    for (int j = 0; j < 4; j++) { accG[rg][nt][j] = 0.f; accT[rg][nt][j] = 0.f; }

            // prologue: LDG A stage 0 (src=xi, kb=0); one float4 per thread
            float4 v0;
            {
                int row = t0 + ar; if (row > N_NODES - 1) row = N_NODES - 1;
                v0 = *(const float4*)(xi + (size_t)row * HIDDEN + acq);
            }

            for (int s = 0; s < 16; s++) {
                // STS stage s (regs -> fp16 smem, double-buffered)
                {
                    uint32_t h0 = pack2(v0.x, v0.y), h1 = pack2(v0.z, v0.w);
                    uint32_t d = smu + (uint32_t)(A_OFF + (s & 1) * A_BUF + ar * AS_ST + acq) * 2u;
                    asm volatile("st.shared.v2.b32 [%0], {%1,%2};"
                                 :: "r"(d), "r"(h0), "r"(h1));
                }
                // LDG A stage s+1
                if (s + 1 < 16) {
                    int s1 = s + 1;
                    const float* src = (s1 < 8) ? xi : xf;
                    int kb = (s1 & 7) * 32;
                    int row = t0 + ar; if (row > N_NODES - 1) row = N_NODES - 1;
                    v0 = *(const float4*)(src + (size_t)row * HIDDEN + kb + acq);
                }
                __syncthreads();

                // ---- compute stage s ----
                const uint32_t aS = aBase + (uint32_t)((s & 1) * A_BUF) * 2u;
                const int kg = s * 32;
                const int kt = (s - 8) * 32;
                const bool p2 = (s >= 8);
                #pragma unroll
                for (int kk = 0; kk < 32; kk += 16) {
                    uint32_t a[2][4];
                    #pragma unroll
                    for (int rg = 0; rg < 2; rg++)
                        ldsm4(a[rg], aS + (uint32_t)(rg * 16 * AS_ST + kk) * 2u);
                    uint32_t bgf[4];
                    ldsm4(bgf, wgBase + (uint32_t)(kg + kk) * 2u);
                    #pragma unroll
                    for (int rg = 0; rg < 2; rg++) {
                        mma16(accG[rg][0], a[rg], bgf[0], bgf[1]);
                        mma16(accG[rg][1], a[rg], bgf[2], bgf[3]);
                    }
                    if (p2) {
                        uint32_t btf[4];
                        ldsm4(btf, wtBase + (uint32_t)(kt + kk) * 2u);
                        #pragma unroll
                        for (int rg = 0; rg < 2; rg++) {
                            mma16(accT[rg][0], a[rg], btf[0], btf[1]);
                            mma16(accT[rg][1], a[rg], btf[2], btf[3]);
                        }
                    }
                }
            }

            // epilogue: sigmoid(gate)*trans, mask tail rows, fold into sums
            int cnt = e - t0; if (cnt > 128) cnt = 128;
            #pragma unroll
            for (int nt = 0; nt < 2; nt++) {
                int cE = nb + nt * 8 + 2 * tig;
                float bgEv = g_bg_pad[cE],     bgOv = g_bg_pad[cE + 1];
                float btEv = g_bt_pad[cE],     btOv = g_bt_pad[cE + 1];
                #pragma unroll
                for (int rg = 0; rg < 2; rg++) {
                    int r0 = rb + rg * 16 + gid;
                    int r1 = r0 + 8;
                    if (r0 < cnt) {
                        float g0 = accG[rg][nt][0] + bgEv;
                        float g1 = accG[rg][nt][1] + bgOv;
                        float t0v = accT[rg][nt][0] + btEv;
                        float t1v = accT[rg][nt][1] + btOv;
                        sumE[nt] += t0v * __fdividef(1.f, 1.f + __expf(-g0));
                        sumO[nt] += t1v * __fdividef(1.f, 1.f + __expf(-g1));
                    }
                    if (r1 < cnt) {
                        float g2 = accG[rg][nt][2] + bgEv;
                        float g3 = accG[rg][nt][3] + bgOv;
                        float t2v = accT[rg][nt][2] + btEv;
                        float t3v = accT[rg][nt][3] + btOv;
                        sumE[nt] += t2v * __fdividef(1.f, 1.f + __expf(-g2));
                        sumO[nt] += t3v * __fdividef(1.f, 1.f + __expf(-g3));
                    }
                }
            }
        }

        // ---- per-graph reduction (sAcc aliases A-buffer smem) ----
        __syncthreads();
        float* sAcc = (float*)(sm + A_OFF);
        if (tid < CP) sAcc[tid] = 0.f;
        __syncthreads();
        #pragma unroll
        for (int nt = 0; nt < 2; nt++) {
            float vE = sumE[nt], vO = sumO[nt];
            #pragma unroll
            for (int m = 4; m <= 16; m <<= 1) {
                vE += __shfl_xor_sync(0xffffffffu, vE, m);
                vO += __shfl_xor_sync(0xffffffffu, vO, m);
            }
            if (gid == 0) {
                int cE = nb + nt * 8 + 2 * tig;
                atomicAdd(&sAcc[cE], vE);
                atomicAdd(&sAcc[cE + 1], vO);
            }
        }
        __syncthreads();
        if (tid < NUM_CLASSES) g_readout[g * NUM_CLASSES + tid] = sAcc[tid];
        __syncthreads();
    }
}

// ---------------- BN + MLP: one block per graph ----------------
__global__ void mlp_kernel(const float* __restrict__ aux,
                           const float* __restrict__ bn_gamma, const float* __restrict__ bn_beta,
                           const float* __restrict__ bn_mean,  const float* __restrict__ bn_var,
                           const float* __restrict__ W1, const float* __restrict__ b1,
                           const float* __restrict__ W2, const float* __restrict__ b2,
                           float* __restrict__ out) {
    __shared__ float sn[D_IN];
    __shared__ float sh[GRAPH_X];
    int g = blockIdx.x, tid = threadIdx.x;
    if (tid < D_IN) {
        float v = (tid < NUM_CLASSES) ? g_readout[g * NUM_CLASSES + tid]
                                      : aux[g * AUX_DIM + (tid - NUM_CLASSES)];
        sn[tid] = (v - bn_mean[tid]) * rsqrtf(bn_var[tid] + 1e-5f) * bn_gamma[tid] + bn_beta[tid];
    }
    __syncthreads();
    {
        float acc = b1[tid];
        #pragma unroll 8
        for (int d = 0; d < D_IN; d++) acc = fmaf(sn[d], W1[d * GRAPH_X + tid], acc);
        sh[tid] = fmaxf(acc, 0.f);
    }
    __syncthreads();
    if (tid < NUM_CLASSES) {
        float acc = b2[tid];
        #pragma unroll 8
        for (int j = 0; j < GRAPH_X; j++) acc = fmaf(sh[j], W2[j * NUM_CLASSES + tid], acc);
        out[g * NUM_CLASSES + tid] = acc;
    }
}

// ---------------- launch ----------------
extern "C" void kernel_launch(void* const* d_in, const int* in_sizes, int n_in,
                              void* d_out, int out_size) {
    int o = (n_in > 4 && in_sizes[4] == 1) ? 1 : 0;
    const float* xi  = (const float*)d_in[0];
    const float* xf  = (const float*)d_in[1];
    const float* aux = (const float*)d_in[2];
    const int*   gl  = (const int*)  d_in[3];
    const float* Wg  = (const float*)d_in[4 + o];
    const float* bg  = (const float*)d_in[5 + o];
    const float* Wt  = (const float*)d_in[6 + o];
    const float* bt  = (const float*)d_in[7 + o];
    const float* bn_gamma = (const float*)d_in[8 + o];
    const float* bn_beta  = (const float*)d_in[9 + o];
    const float* bn_mean  = (const float*)d_in[10 + o];
    const float* bn_var   = (const float*)d_in[11 + o];
    const float* W1 = (const float*)d_in[12 + o];
    const float* b1 = (const float*)d_in[13 + o];
    const float* W2 = (const float*)d_in[14 + o];
    const float* b2 = (const float*)d_in[15 + o];
    float* out = (float*)d_out;

    cudaFuncSetAttribute(fused_node_tc, cudaFuncAttributeMaxDynamicSharedMemorySize, DYN_BYTES);

    int dev = 0, nsm = 148;
    cudaGetDevice(&dev);
    cudaDeviceGetAttribute(&nsm, cudaDevAttrMultiProcessorCount, dev);

    prep_kernel<<<(CP * 2 * HIDDEN + 255) / 256, 256>>>(Wg, bg, Wt, bt);
    starts_kernel<<<(NUM_GRAPHS + 1 + 255) / 256, 256>>>(gl, N_NODES);
    align_dummy_kernel<<<1, 32>>>();   // keeps ncu -s window on fused_node_tc
    fused_node_tc<<<nsm, 1024, DYN_BYTES>>>(xi, xf);
    mlp_kernel<<<NUM_GRAPHS, GRAPH_X>>>(aux, bn_gamma, bn_beta, bn_mean, bn_var,
                                        W1, b1, W2, b2, out);
}